// round 3
// baseline (speedup 1.0000x reference)
#include <cuda_runtime.h>

#define T_LEN 32768
#define D_IN  512
#define HID   20
#define G4    80   // 4*HID

// Scratch (static device arrays; no allocation)
// Layout: g_xg[t*80 + unit*4 + {i,f,g,o}]  (unit-major gate interleave)
__device__ float g_xg[T_LEN * G4];
__device__ float g_h [T_LEN * HID];

typedef unsigned long long ull;

__device__ __forceinline__ ull pack2(float lo, float hi) {
    ull r;
    asm("mov.b64 %0, {%1, %2};" : "=l"(r) : "f"(lo), "f"(hi));
    return r;
}
__device__ __forceinline__ void unpack2(ull v, float& lo, float& hi) {
    asm("mov.b64 {%0, %1}, %2;" : "=f"(lo), "=f"(hi) : "l"(v));
}
__device__ __forceinline__ void ffma2(ull& acc, ull a, ull b) {
    asm("fma.rn.f32x2 %0, %1, %2, %0;" : "+l"(acc) : "l"(a), "l"(b));
}
__device__ __forceinline__ ull fadd2(ull a, ull b) {
    ull r;
    asm("add.rn.f32x2 %0, %1, %2;" : "=l"(r) : "l"(a), "l"(b));
    return r;
}

// ---------------------------------------------------------------------------
// Kernel A: xg[t][unit*4+q] = sum_k x[t][k]*W_ih[q*20+unit][k] + bias
// ---------------------------------------------------------------------------
__global__ void gemm_xg_kernel(const float* __restrict__ x,
                               const float* __restrict__ W_ih,
                               const float* __restrict__ b_ih,
                               const float* __restrict__ b_hh) {
    __shared__ float xs[64][64];
    __shared__ float ws[80][65];

    const int tid = threadIdx.x;
    const int t0  = blockIdx.x * 64;
    const int rg  = tid >> 4;
    const int gg  = tid & 15;

    float acc[4][5];
#pragma unroll
    for (int r = 0; r < 4; ++r)
#pragma unroll
        for (int i = 0; i < 5; ++i) acc[r][i] = 0.f;

    const float4* x4 = (const float4*)x;

    for (int kc = 0; kc < D_IN; kc += 64) {
#pragma unroll
        for (int it = 0; it < 4; ++it) {
            int idx = tid + it * 256;
            int row = idx >> 4;
            int c4  = idx & 15;
            float4 v = x4[(size_t)(t0 + row) * (D_IN / 4) + (kc >> 2) + c4];
            *(float4*)&xs[row][c4 * 4] = v;
        }
#pragma unroll
        for (int it = 0; it < 20; ++it) {
            int idx = tid + it * 256;
            int gq  = idx >> 6;
            int kk  = idx & 63;
            ws[gq][kk] = W_ih[gq * D_IN + kc + kk];
        }
        __syncthreads();

#pragma unroll 4
        for (int k = 0; k < 64; ++k) {
            float xv[4], wv[5];
#pragma unroll
            for (int r = 0; r < 4; ++r) xv[r] = xs[rg * 4 + r][k];
#pragma unroll
            for (int i = 0; i < 5; ++i) wv[i] = ws[gg * 5 + i][k];
#pragma unroll
            for (int r = 0; r < 4; ++r)
#pragma unroll
                for (int i = 0; i < 5; ++i)
                    acc[r][i] = fmaf(xv[r], wv[i], acc[r][i]);
        }
        __syncthreads();
    }

#pragma unroll
    for (int r = 0; r < 4; ++r) {
        int row = t0 + rg * 4 + r;
#pragma unroll
        for (int i = 0; i < 5; ++i) {
            int gate = gg * 5 + i;        // = q*20 + unit
            int q    = gate / HID;
            int unit = gate % HID;
            g_xg[(size_t)row * G4 + unit * 4 + q] =
                acc[r][i] + b_ih[gate] + b_hh[gate];
        }
    }
}

// ---------------------------------------------------------------------------
// Kernel B: 4-warp LSTM scan, ONE bar per step.
//   warp w owns units 5w..5w+4; lane l: unit = 5w + (l>>2), gate q = l&3
//   matvec: LDS.64 h-pairs (broadcast) + 10 FFMA2 in (even,odd) pair form
//   update: intra-warp shfl of the 4 gate activations, redundant per group
// ---------------------------------------------------------------------------
__global__ void __launch_bounds__(128, 1)
lstm_scan_kernel(const float* __restrict__ h_state,
                 const float* __restrict__ c_state,
                 const float* __restrict__ W_hh,
                 float* __restrict__ out) {
    __shared__ __align__(16) float hbuf[2][HID];

    const int tid = threadIdx.x;
    const int w   = tid >> 5;
    const int l   = tid & 31;
    const int le  = (l < HID) ? l : HID - 1;   // lanes 20..31 mirror lane 19
    const int q   = le & 3;                    // gate: 0=i 1=f 2=g 3=o
    const int u   = 5 * w + (le >> 2);         // unit 0..19
    const int row = q * HID + u;               // W_hh row
    const int base = l & ~3;                   // 4-lane group base

    // weight pairs: wp[m] = (W[row][2m], W[row][2m+1])
    ull wp[10];
#pragma unroll
    for (int m = 0; m < 10; ++m)
        wp[m] = pack2(W_hh[row * HID + 2 * m], W_hh[row * HID + 2 * m + 1]);

    // unified activation constants: q==2 (g-gate) -> tanh, else sigmoid
    const float Aa = (q == 2) ? 2.f : 1.f;
    const float Cc = (q == 2) ? -1.f : 0.f;

    float c = c_state[u];
    float h = 0.f;
    if (tid < HID) hbuf[0][tid] = h_state[tid];
    __syncthreads();

    const int xcol = 20 * w + le;              // == unit*4 + q within a row of 80
    float v0 = g_xg[(size_t)0 * G4 + xcol];
    float v1 = g_xg[(size_t)1 * G4 + xcol];
    float v2 = g_xg[(size_t)2 * G4 + xcol];

    int p = 0;
    const unsigned FULL = 0xffffffffu;

    for (int t = 0; t < T_LEN; ++t) {
        // matvec over h pairs (LDS.64 broadcast, conflict-free)
        const ull* hp = (const ull*)hbuf[p];
        ull a0 = pack2(v0, 0.f);
        ull a1 = pack2(0.f, 0.f);
#pragma unroll
        for (int m = 0; m < 10; m += 2) {
            ffma2(a0, wp[m],     hp[m]);
            ffma2(a1, wp[m + 1], hp[m + 1]);
        }
        ull as = fadd2(a0, a1);
        float s0, s1;
        unpack2(as, s0, s1);
        float pre = s0 + s1;

        // unified activation (accurate, exp-based)
        float act = fmaf(Aa, __fdividef(1.f, 1.f + __expf(-Aa * pre)), Cc);

        // rotate xg prefetch ring (depth 3, covers L2 latency)
        v0 = v1; v1 = v2;
        int tn = (t + 3 < T_LEN) ? t + 3 : T_LEN - 1;
        v2 = g_xg[(size_t)tn * G4 + xcol];

        // gather the 4 gates of this unit (intra-warp, all lanes participate)
        float i_ = __shfl_sync(FULL, act, base);
        float f_ = __shfl_sync(FULL, act, base + 1);
        float g_ = __shfl_sync(FULL, act, base + 2);
        float o_ = __shfl_sync(FULL, act, base + 3);

        c = fmaf(f_, c, i_ * g_);
        float th = fmaf(2.f, __fdividef(1.f, 1.f + __expf(-2.f * c)), -1.f);
        h = o_ * th;

        p ^= 1;
        if (q == 0 && l < HID) {
            hbuf[p][u] = h;
            g_h[(size_t)t * HID + u] = h;   // fire-and-forget
        }
        __syncthreads();   // the ONE bar: drains STS, releases next step
    }

    if (q == 0 && l < HID) {
        out[T_LEN + u]       = h;
        out[T_LEN + HID + u] = c;
    }
}

// ---------------------------------------------------------------------------
// Kernel C: y[t] = h[t,:] . W_out + b_out
// ---------------------------------------------------------------------------
__global__ void out_proj_kernel(const float* __restrict__ W_out,
                                const float* __restrict__ b_out,
                                float* __restrict__ out) {
    __shared__ float w[HID];
    __shared__ float b0;
    if (threadIdx.x < HID) w[threadIdx.x] = W_out[threadIdx.x];
    if (threadIdx.x == 0)  b0 = b_out[0];
    __syncthreads();

    int t = blockIdx.x * blockDim.x + threadIdx.x;
    if (t < T_LEN) {
        const float4* hv = (const float4*)(g_h + (size_t)t * HID);
        float acc = 0.f;
#pragma unroll
        for (int qq = 0; qq < 5; ++qq) {
            float4 v = hv[qq];
            acc = fmaf(v.x, w[qq * 4 + 0], acc);
            acc = fmaf(v.y, w[qq * 4 + 1], acc);
            acc = fmaf(v.z, w[qq * 4 + 2], acc);
            acc = fmaf(v.w, w[qq * 4 + 3], acc);
        }
        out[t] = acc + b0;
    }
}

// ---------------------------------------------------------------------------
extern "C" void kernel_launch(void* const* d_in, const int* in_sizes, int n_in,
                              void* d_out, int out_size) {
    const float* x       = (const float*)d_in[0];
    const float* h_state = (const float*)d_in[1];
    const float* c_state = (const float*)d_in[2];
    const float* W_ih    = (const float*)d_in[3];
    const float* W_hh    = (const float*)d_in[4];
    const float* b_ih    = (const float*)d_in[5];
    const float* b_hh    = (const float*)d_in[6];
    const float* W_out   = (const float*)d_in[7];
    const float* b_out   = (const float*)d_in[8];
    float* out = (float*)d_out;

    gemm_xg_kernel<<<T_LEN / 64, 256>>>(x, W_ih, b_ih, b_hh);
    lstm_scan_kernel<<<1, 128>>>(h_state, c_state, W_hh, out);
    out_proj_kernel<<<(T_LEN + 255) / 256, 256>>>(W_out, b_out, out);
}

// round 4
// speedup vs baseline: 1.7417x; 1.7417x over previous
#include <cuda_runtime.h>

#define T_LEN 32768
#define D_IN  512
#define HID   20
#define G4    80   // 4*HID

// Scratch (static device arrays; no allocation)
// Layout: g_xg[t*80 + unit*4 + {i,f,g,o}]
__device__ float g_xg[T_LEN * G4];
__device__ float g_h [T_LEN * HID];

typedef unsigned long long ull;

__device__ __forceinline__ ull pack2(float lo, float hi) {
    ull r;
    asm("mov.b64 %0, {%1, %2};" : "=l"(r) : "f"(lo), "f"(hi));
    return r;
}
__device__ __forceinline__ void unpack2(ull v, float& lo, float& hi) {
    asm("mov.b64 {%0, %1}, %2;" : "=f"(lo), "=f"(hi) : "l"(v));
}
__device__ __forceinline__ void ffma2(ull& acc, ull a, ull b) {
    asm("fma.rn.f32x2 %0, %1, %2, %0;" : "+l"(acc) : "l"(a), "l"(b));
}
__device__ __forceinline__ ull fadd2(ull a, ull b) {
    ull r;
    asm("add.rn.f32x2 %0, %1, %2;" : "=l"(r) : "l"(a), "l"(b));
    return r;
}
__device__ __forceinline__ float tanh_mufu(float x) {
    float r;
    asm("tanh.approx.f32 %0, %1;" : "=f"(r) : "f"(x));
    return r;
}
__device__ __forceinline__ float sig_mufu(float x) {
    return fmaf(0.5f, tanh_mufu(0.5f * x), 0.5f);
}

// ---------------------------------------------------------------------------
// Kernel A: xg[t][unit*4+q] = sum_k x[t][k]*W_ih[q*20+unit][k] + bias
// ---------------------------------------------------------------------------
__global__ void gemm_xg_kernel(const float* __restrict__ x,
                               const float* __restrict__ W_ih,
                               const float* __restrict__ b_ih,
                               const float* __restrict__ b_hh) {
    __shared__ float xs[64][64];
    __shared__ float ws[80][65];

    const int tid = threadIdx.x;
    const int t0  = blockIdx.x * 64;
    const int rg  = tid >> 4;
    const int gg  = tid & 15;

    float acc[4][5];
#pragma unroll
    for (int r = 0; r < 4; ++r)
#pragma unroll
        for (int i = 0; i < 5; ++i) acc[r][i] = 0.f;

    const float4* x4 = (const float4*)x;

    for (int kc = 0; kc < D_IN; kc += 64) {
#pragma unroll
        for (int it = 0; it < 4; ++it) {
            int idx = tid + it * 256;
            int row = idx >> 4;
            int c4  = idx & 15;
            float4 v = x4[(size_t)(t0 + row) * (D_IN / 4) + (kc >> 2) + c4];
            *(float4*)&xs[row][c4 * 4] = v;
        }
#pragma unroll
        for (int it = 0; it < 20; ++it) {
            int idx = tid + it * 256;
            int gq  = idx >> 6;
            int kk  = idx & 63;
            ws[gq][kk] = W_ih[gq * D_IN + kc + kk];
        }
        __syncthreads();

#pragma unroll 4
        for (int k = 0; k < 64; ++k) {
            float xv[4], wv[5];
#pragma unroll
            for (int r = 0; r < 4; ++r) xv[r] = xs[rg * 4 + r][k];
#pragma unroll
            for (int i = 0; i < 5; ++i) wv[i] = ws[gg * 5 + i][k];
#pragma unroll
            for (int r = 0; r < 4; ++r)
#pragma unroll
                for (int i = 0; i < 5; ++i)
                    acc[r][i] = fmaf(xv[r], wv[i], acc[r][i]);
        }
        __syncthreads();
    }

#pragma unroll
    for (int r = 0; r < 4; ++r) {
        int row = t0 + rg * 4 + r;
#pragma unroll
        for (int i = 0; i < 5; ++i) {
            int gate = gg * 5 + i;        // = q*20 + unit
            int q    = gate / HID;
            int unit = gate % HID;
            g_xg[(size_t)row * G4 + unit * 4 + q] =
                acc[r][i] + b_ih[gate] + b_hh[gate];
        }
    }
}

// ---------------------------------------------------------------------------
// Kernel B: single-WARP scan. Lane u owns unit u (u<20).
//  - h distributed via duplicated smem (STS.64 of (h,h), LDS.64 broadcast)
//  - packed f32x2 FMAs, MUFU.TANH activations, zero block barriers
// ---------------------------------------------------------------------------
__global__ void __launch_bounds__(32, 1)
lstm_scan_kernel(const float* __restrict__ h_state,
                 const float* __restrict__ c_state,
                 const float* __restrict__ W_hh,
                 float* __restrict__ out) {
    __shared__ __align__(16) float2 hdup[2][HID + 4];   // duplicated h, double-buffered

    const int l = threadIdx.x;
    const int u = (l < HID) ? l : HID - 1;   // lanes 20..31 mirror lane 19

    // Packed weights: w_if[k]=(W[u][k],W[u+20][k]); w_go[k]=(W[u+40][k],W[u+60][k])
    ull w_if[HID], w_go[HID];
#pragma unroll
    for (int k = 0; k < HID; ++k) {
        w_if[k] = pack2(W_hh[u * HID + k],        W_hh[(u + 20) * HID + k]);
        w_go[k] = pack2(W_hh[(u + 40) * HID + k], W_hh[(u + 60) * HID + k]);
    }

    float c = c_state[u];
    float h = h_state[u];
    if (l < HID) {
        float2 d; d.x = h; d.y = h;
        hdup[0][l] = d;
    }
    __syncwarp();

    const float4* xg4 = (const float4*)g_xg;

    // prefetch ring, depth 4
    float4 ring[4];
#pragma unroll
    for (int i = 0; i < 4; ++i) ring[i] = __ldg(&xg4[(size_t)i * HID + u]);

    int p = 0;

#pragma unroll 4
    for (int t = 0; t < T_LEN; ++t) {
        const float4 xv = ring[t & 3];
        int tn = t + 4;
        if (tn >= T_LEN) tn = T_LEN - 1;
        ring[t & 3] = __ldg(&xg4[(size_t)tn * HID + u]);

        const ull* hp = (const ull*)hdup[p];   // (h_k, h_k) 64-bit broadcasts

        // 4 interleaved accumulator chains
        ull a_if0 = pack2(xv.x, xv.y), a_if1 = pack2(0.f, 0.f);
        ull a_go0 = pack2(xv.z, xv.w), a_go1 = pack2(0.f, 0.f);
#pragma unroll
        for (int k = 0; k < HID; k += 2) {
            ffma2(a_if0, w_if[k],     hp[k]);
            ffma2(a_go0, w_go[k],     hp[k]);
            ffma2(a_if1, w_if[k + 1], hp[k + 1]);
            ffma2(a_go1, w_go[k + 1], hp[k + 1]);
        }
        ull a_if = fadd2(a_if0, a_if1);
        ull a_go = fadd2(a_go0, a_go1);

        float pi, pf, pg, po;
        unpack2(a_if, pi, pf);
        unpack2(a_go, pg, po);

        float i_s = sig_mufu(pi);
        float f_s = sig_mufu(pf);
        float o_s = sig_mufu(po);
        float g_t = tanh_mufu(pg);

        c = fmaf(f_s, c, i_s * g_t);
        h = o_s * tanh_mufu(c);

        p ^= 1;
        if (l < HID) {
            float2 d; d.x = h; d.y = h;
            hdup[p][l] = d;
            g_h[(size_t)t * HID + l] = h;   // fire-and-forget
        }
        __syncwarp();
    }

    if (l < HID) {
        out[T_LEN + l]       = h;
        out[T_LEN + HID + l] = c;
    }
}

// ---------------------------------------------------------------------------
// Kernel C: y[t] = h[t,:] . W_out + b_out
// ---------------------------------------------------------------------------
__global__ void out_proj_kernel(const float* __restrict__ W_out,
                                const float* __restrict__ b_out,
                                float* __restrict__ out) {
    __shared__ float w[HID];
    __shared__ float b0;
    if (threadIdx.x < HID) w[threadIdx.x] = W_out[threadIdx.x];
    if (threadIdx.x == 0)  b0 = b_out[0];
    __syncthreads();

    int t = blockIdx.x * blockDim.x + threadIdx.x;
    if (t < T_LEN) {
        const float4* hv = (const float4*)(g_h + (size_t)t * HID);
        float acc = 0.f;
#pragma unroll
        for (int q = 0; q < 5; ++q) {
            float4 v = hv[q];
            acc = fmaf(v.x, w[q * 4 + 0], acc);
            acc = fmaf(v.y, w[q * 4 + 1], acc);
            acc = fmaf(v.z, w[q * 4 + 2], acc);
            acc = fmaf(v.w, w[q * 4 + 3], acc);
        }
        out[t] = acc + b0;
    }
}

// ---------------------------------------------------------------------------
extern "C" void kernel_launch(void* const* d_in, const int* in_sizes, int n_in,
                              void* d_out, int out_size) {
    const float* x       = (const float*)d_in[0];
    const float* h_state = (const float*)d_in[1];
    const float* c_state = (const float*)d_in[2];
    const float* W_ih    = (const float*)d_in[3];
    const float* W_hh    = (const float*)d_in[4];
    const float* b_ih    = (const float*)d_in[5];
    const float* b_hh    = (const float*)d_in[6];
    const float* W_out   = (const float*)d_in[7];
    const float* b_out   = (const float*)d_in[8];
    float* out = (float*)d_out;

    gemm_xg_kernel<<<T_LEN / 64, 256>>>(x, W_ih, b_ih, b_hh);
    lstm_scan_kernel<<<1, 32>>>(h_state, c_state, W_hh, out);
    out_proj_kernel<<<(T_LEN + 255) / 256, 256>>>(W_out, b_out, out);
}

// round 5
// speedup vs baseline: 1.8297x; 1.0505x over previous
#include <cuda_runtime.h>

#define T_LEN 32768
#define D_IN  512
#define HID   20
#define G4    80   // 4*HID

// Scratch (static device arrays; no allocation)
// g_xg: [t][gate], gate = q*20+u (q: 0=i,1=f,2=g,3=o), PRESCALED x0.5 except g-gates
__device__ float g_xg[T_LEN * G4];
// g_hT: transposed hidden states [u][t]
__device__ float g_hT[HID * T_LEN];

typedef unsigned long long ull;

__device__ __forceinline__ ull pack2(float lo, float hi) {
    ull r;
    asm("mov.b64 %0, {%1, %2};" : "=l"(r) : "f"(lo), "f"(hi));
    return r;
}
__device__ __forceinline__ void unpack2(ull v, float& lo, float& hi) {
    asm("mov.b64 {%0, %1}, %2;" : "=f"(lo), "=f"(hi) : "l"(v));
}
__device__ __forceinline__ void ffma2(ull& acc, ull a, ull b) {
    asm("fma.rn.f32x2 %0, %1, %2, %0;" : "+l"(acc) : "l"(a), "l"(b));
}
__device__ __forceinline__ ull fadd2(ull a, ull b) {
    ull r;
    asm("add.rn.f32x2 %0, %1, %2;" : "=l"(r) : "l"(a), "l"(b));
    return r;
}
__device__ __forceinline__ ull mul2(ull a, ull b) {
    ull r;
    asm("mul.rn.f32x2 %0, %1, %2;" : "=l"(r) : "l"(a), "l"(b));
    return r;
}
__device__ __forceinline__ float tanh_mufu(float x) {
    float r;
    asm("tanh.approx.f32 %0, %1;" : "=f"(r) : "f"(x));
    return r;
}

// ---------------------------------------------------------------------------
// Kernel A: xg[t][gate] = (x[t,:].W_ih[gate,:] + b) * prescale(gate)
// ---------------------------------------------------------------------------
__global__ void gemm_xg_kernel(const float* __restrict__ x,
                               const float* __restrict__ W_ih,
                               const float* __restrict__ b_ih,
                               const float* __restrict__ b_hh) {
    __shared__ float xs[64][64];
    __shared__ float ws[80][65];

    const int tid = threadIdx.x;
    const int t0  = blockIdx.x * 64;
    const int rg  = tid >> 4;
    const int gg  = tid & 15;

    float acc[4][5];
#pragma unroll
    for (int r = 0; r < 4; ++r)
#pragma unroll
        for (int i = 0; i < 5; ++i) acc[r][i] = 0.f;

    const float4* x4 = (const float4*)x;

    for (int kc = 0; kc < D_IN; kc += 64) {
#pragma unroll
        for (int it = 0; it < 4; ++it) {
            int idx = tid + it * 256;
            int row = idx >> 4;
            int c4  = idx & 15;
            float4 v = x4[(size_t)(t0 + row) * (D_IN / 4) + (kc >> 2) + c4];
            *(float4*)&xs[row][c4 * 4] = v;
        }
#pragma unroll
        for (int it = 0; it < 20; ++it) {
            int idx = tid + it * 256;
            int gq  = idx >> 6;
            int kk  = idx & 63;
            ws[gq][kk] = W_ih[gq * D_IN + kc + kk];
        }
        __syncthreads();

#pragma unroll 4
        for (int k = 0; k < 64; ++k) {
            float xv[4], wv[5];
#pragma unroll
            for (int r = 0; r < 4; ++r) xv[r] = xs[rg * 4 + r][k];
#pragma unroll
            for (int i = 0; i < 5; ++i) wv[i] = ws[gg * 5 + i][k];
#pragma unroll
            for (int r = 0; r < 4; ++r)
#pragma unroll
                for (int i = 0; i < 5; ++i)
                    acc[r][i] = fmaf(xv[r], wv[i], acc[r][i]);
        }
        __syncthreads();
    }

#pragma unroll
    for (int r = 0; r < 4; ++r) {
        int row = t0 + rg * 4 + r;
#pragma unroll
        for (int i = 0; i < 5; ++i) {
            int gate = gg * 5 + i;   // q*20+u
            float scale = (gate >= 40 && gate < 60) ? 1.f : 0.5f;  // g: 1, i/f/o: 0.5
            g_xg[(size_t)row * G4 + gate] =
                (acc[r][i] + b_ih[gate] + b_hh[gate]) * scale;
        }
    }
}

// ---------------------------------------------------------------------------
// Kernel B: single-warp scan, k-paired 3-slot matvec (30 FFMA2/step).
//   slot0: lane l -> gate l         (i_l for l<20, f_{l-20} for l>=20)  [all sigma]
//   slot1: lane l -> gate 40+l (l<20, = g_l, tanh) ; l+12 (l=20..27, f) ; l+32 (l>=28, o)
//   slot2: lane l -> gate 64+l (l<16, = o_{4+l})
//   i,g local to owner lane u; f,o gathered via 4 shfl + 2 sel.
// ---------------------------------------------------------------------------
struct F3 { float a, b, d; };

__device__ __forceinline__ F3 run_chains(const float* hbase,
                                         const ull* w0, const ull* w1, const ull* w2,
                                         float x0, float x1, float x2) {
    const ull* hp = (const ull*)hbase;   // (h_2m, h_2m+1) pairs
    ull a0 = pack2(x0, 0.f);
    ull b0 = pack2(x1, 0.f);
    ull d0 = pack2(x2, 0.f);
    ull he = hp[0], ho = hp[1];
    ffma2(a0, w0[0], he);
    ffma2(b0, w1[0], he);
    ffma2(d0, w2[0], he);
    ull a1 = mul2(w0[1], ho);
    ull b1 = mul2(w1[1], ho);
    ull d1 = mul2(w2[1], ho);
#pragma unroll
    for (int m = 2; m < 10; m += 2) {
        ull hm = hp[m], hn = hp[m + 1];
        ffma2(a0, w0[m], hm); ffma2(a1, w0[m + 1], hn);
        ffma2(b0, w1[m], hm); ffma2(b1, w1[m + 1], hn);
        ffma2(d0, w2[m], hm); ffma2(d1, w2[m + 1], hn);
    }
    float lo, hi;
    F3 r;
    unpack2(fadd2(a0, a1), lo, hi); r.a = lo + hi;
    unpack2(fadd2(b0, b1), lo, hi); r.b = lo + hi;
    unpack2(fadd2(d0, d1), lo, hi); r.d = lo + hi;
    return r;
}

__global__ void __launch_bounds__(32, 1)
lstm_scan_kernel(const float* __restrict__ h_state,
                 const float* __restrict__ c_state,
                 const float* __restrict__ W_hh,
                 float* __restrict__ out) {
    __shared__ __align__(16) float hsm[2][24];

    const int l = threadIdx.x;
    const int u = (l < HID) ? l : HID - 1;
    const unsigned FULLM = 0xffffffffu;

    const int G0 = l;
    const int G1 = (l < 20) ? (40 + l) : ((l < 28) ? (l + 12) : (l + 32));
    const int G2 = (l < 16) ? (64 + l) : 79;

    // slot1 activation consts: tanh for l<20 (g), sigma otherwise
    const float B1 = (l < 20) ? 1.0f : 0.5f;
    const float C1 = (l < 20) ? 0.0f : 0.5f;

    // k-paired weights, prescaled (sigma rows x0.5; inactive slot2 lanes x0)
    ull w0[10], w1[10], w2[10];
    const float s1v = (l < 20) ? 1.f : 0.5f;
    const float s2v = (l < 16) ? 0.5f : 0.f;
#pragma unroll
    for (int m = 0; m < 10; ++m) {
        w0[m] = pack2(0.5f * W_hh[G0 * HID + 2 * m], 0.5f * W_hh[G0 * HID + 2 * m + 1]);
        w1[m] = pack2(s1v  * W_hh[G1 * HID + 2 * m], s1v  * W_hh[G1 * HID + 2 * m + 1]);
        w2[m] = pack2(s2v  * W_hh[G2 * HID + 2 * m], s2v  * W_hh[G2 * HID + 2 * m + 1]);
    }

    float c = c_state[u];
    float h = 0.f;
    if (l < HID) hsm[0][l] = h_state[l];
    __syncwarp();

    const float* xp0 = g_xg + G0;
    const float* xp1 = g_xg + G1;
    const float* xp2 = g_xg + G2;

    float rgA[4], rgB[4], rgC[4];
#pragma unroll
    for (int i = 0; i < 4; ++i) {
        size_t off = (size_t)i * G4;
        rgA[i] = __ldg(xp0 + off);
        rgB[i] = __ldg(xp1 + off);
        rgC[i] = __ldg(xp2 + off);
    }

#define STEP(P, COMP, RBUF, WBUF) {                                         \
    float x0 = rgA[P], x1 = rgB[P], x2 = rgC[P];                            \
    int tp = t + (P) + 4; if (tp > T_LEN - 1) tp = T_LEN - 1;               \
    size_t off = (size_t)tp * G4;                                           \
    rgA[P] = __ldg(xp0 + off);                                              \
    rgB[P] = __ldg(xp1 + off);                                              \
    rgC[P] = __ldg(xp2 + off);                                              \
    F3 pre = run_chains(hsm[RBUF], w0, w1, w2, x0, x1, x2);                 \
    float act0 = fmaf(0.5f, tanh_mufu(pre.a), 0.5f);                        \
    float act1 = fmaf(B1,   tanh_mufu(pre.b), C1);                          \
    float act2 = fmaf(0.5f, tanh_mufu(pre.d), 0.5f);                        \
    float fA = __shfl_sync(FULLM, act0, l + 20);                            \
    float fB = __shfl_sync(FULLM, act1, l + 8);                             \
    float fv = (l < 12) ? fA : fB;                                          \
    float oA = __shfl_sync(FULLM, act1, l + 28);                            \
    float oB = __shfl_sync(FULLM, act2, l - 4);                             \
    float ov = (l < 4) ? oA : oB;                                           \
    c = fmaf(fv, c, act0 * act1);                                           \
    h = ov * tanh_mufu(c);                                                  \
    if (l < HID) hsm[WBUF][l] = h;                                          \
    __syncwarp();                                                           \
    COMP = h; }

    for (int t = 0; t < T_LEN; t += 4) {
        float4 hb;
        STEP(0, hb.x, 0, 1)
        STEP(1, hb.y, 1, 0)
        STEP(2, hb.z, 0, 1)
        STEP(3, hb.w, 1, 0)
        if (l < HID)
            *(float4*)(g_hT + (size_t)l * T_LEN + t) = hb;
    }
#undef STEP

    if (l < HID) {
        out[T_LEN + l]       = h;
        out[T_LEN + HID + l] = c;
    }
}

// ---------------------------------------------------------------------------
// Kernel C: y[t] = sum_u g_hT[u][t] * W_out[u] + b_out   (transposed reads)
// ---------------------------------------------------------------------------
__global__ void out_proj_kernel(const float* __restrict__ W_out,
                                const float* __restrict__ b_out,
                                float* __restrict__ out) {
    __shared__ float w[HID];
    __shared__ float b0;
    if (threadIdx.x < HID) w[threadIdx.x] = W_out[threadIdx.x];
    if (threadIdx.x == 0)  b0 = b_out[0];
    __syncthreads();

    int t = blockIdx.x * blockDim.x + threadIdx.x;
    if (t < T_LEN) {
        float acc = 0.f;
#pragma unroll
        for (int uu = 0; uu < HID; ++uu)
            acc = fmaf(g_hT[(size_t)uu * T_LEN + t], w[uu], acc);
        out[t] = acc + b0;
    }
}

// ---------------------------------------------------------------------------
extern "C" void kernel_launch(void* const* d_in, const int* in_sizes, int n_in,
                              void* d_out, int out_size) {
    const float* x       = (const float*)d_in[0];
    const float* h_state = (const float*)d_in[1];
    const float* c_state = (const float*)d_in[2];
    const float* W_ih    = (const float*)d_in[3];
    const float* W_hh    = (const float*)d_in[4];
    const float* b_ih    = (const float*)d_in[5];
    const float* b_hh    = (const float*)d_in[6];
    const float* W_out   = (const float*)d_in[7];
    const float* b_out   = (const float*)d_in[8];
    float* out = (float*)d_out;

    gemm_xg_kernel<<<T_LEN / 64, 256>>>(x, W_ih, b_ih, b_hh);
    lstm_scan_kernel<<<1, 32>>>(h_state, c_state, W_hh, out);
    out_proj_kernel<<<(T_LEN + 255) / 256, 256>>>(W_out, b_out, out);
}

// round 6
// speedup vs baseline: 1.9555x; 1.0688x over previous
#include <cuda_runtime.h>

#define T_LEN 32768
#define D_IN  512
#define HID   20
#define G4    80   // 4*HID

// Scratch (static device arrays; no allocation)
// g_xgp: [t][128], col = lane*4 + slot. Lane l<20: slots {i_l,f_l,g_l,pad}.
// Lane l>=20: slots {o_{l-20}, o_{l-12}, 0, pad}. sigma-gates prescaled x0.5.
__device__ float g_xgp[(size_t)T_LEN * 128];
// g_hT: transposed hidden states [u][t]
__device__ float g_hT[HID * T_LEN];

typedef unsigned long long ull;

__device__ __forceinline__ ull pack2(float lo, float hi) {
    ull r;
    asm("mov.b64 %0, {%1, %2};" : "=l"(r) : "f"(lo), "f"(hi));
    return r;
}
__device__ __forceinline__ void unpack2(ull v, float& lo, float& hi) {
    asm("mov.b64 {%0, %1}, %2;" : "=f"(lo), "=f"(hi) : "l"(v));
}
__device__ __forceinline__ void ffma2(ull& acc, ull a, ull b) {
    asm("fma.rn.f32x2 %0, %1, %2, %0;" : "+l"(acc) : "l"(a), "l"(b));
}
__device__ __forceinline__ ull fadd2(ull a, ull b) {
    ull r;
    asm("add.rn.f32x2 %0, %1, %2;" : "=l"(r) : "l"(a), "l"(b));
    return r;
}
__device__ __forceinline__ ull mul2(ull a, ull b) {
    ull r;
    asm("mul.rn.f32x2 %0, %1, %2;" : "=l"(r) : "l"(a), "l"(b));
    return r;
}
__device__ __forceinline__ float tanh_mufu(float x) {
    float r;
    asm("tanh.approx.f32 %0, %1;" : "=f"(r) : "f"(x));
    return r;
}

// ---------------------------------------------------------------------------
// Kernel A: gemm + scatter into the per-lane packed layout.
// ---------------------------------------------------------------------------
__global__ void gemm_xg_kernel(const float* __restrict__ x,
                               const float* __restrict__ W_ih,
                               const float* __restrict__ b_ih,
                               const float* __restrict__ b_hh) {
    __shared__ float xs[64][64];
    __shared__ float ws[80][65];

    const int tid = threadIdx.x;
    const int t0  = blockIdx.x * 64;
    const int rg  = tid >> 4;
    const int gg  = tid & 15;

    // zero unused columns of this block's 64 rows:
    // pad col lane*4+3 (32 lanes) + upper-lane slot2 col (20+j)*4+2 (12 lanes)
    for (int idx = tid; idx < 64 * 44; idx += 256) {
        int row = idx / 44;
        int k   = idx % 44;
        int col = (k < 32) ? (k * 4 + 3) : ((20 + (k - 32)) * 4 + 2);
        g_xgp[(size_t)(t0 + row) * 128 + col] = 0.f;
    }

    float acc[4][5];
#pragma unroll
    for (int r = 0; r < 4; ++r)
#pragma unroll
        for (int i = 0; i < 5; ++i) acc[r][i] = 0.f;

    const float4* x4 = (const float4*)x;

    for (int kc = 0; kc < D_IN; kc += 64) {
#pragma unroll
        for (int it = 0; it < 4; ++it) {
            int idx = tid + it * 256;
            int row = idx >> 4;
            int c4  = idx & 15;
            float4 v = x4[(size_t)(t0 + row) * (D_IN / 4) + (kc >> 2) + c4];
            *(float4*)&xs[row][c4 * 4] = v;
        }
#pragma unroll
        for (int it = 0; it < 20; ++it) {
            int idx = tid + it * 256;
            int gq  = idx >> 6;
            int kk  = idx & 63;
            ws[gq][kk] = W_ih[gq * D_IN + kc + kk];
        }
        __syncthreads();

#pragma unroll 4
        for (int k = 0; k < 64; ++k) {
            float xv[4], wv[5];
#pragma unroll
            for (int r = 0; r < 4; ++r) xv[r] = xs[rg * 4 + r][k];
#pragma unroll
            for (int i = 0; i < 5; ++i) wv[i] = ws[gg * 5 + i][k];
#pragma unroll
            for (int r = 0; r < 4; ++r)
#pragma unroll
                for (int i = 0; i < 5; ++i)
                    acc[r][i] = fmaf(xv[r], wv[i], acc[r][i]);
        }
        __syncthreads();
    }

#pragma unroll
    for (int r = 0; r < 4; ++r) {
        size_t rowoff = (size_t)(t0 + rg * 4 + r) * 128;
#pragma unroll
        for (int i = 0; i < 5; ++i) {
            int gate = gg * 5 + i;   // q*20+u
            int q    = gate / HID;
            int u    = gate % HID;
            float val = (acc[r][i] + b_ih[gate] + b_hh[gate]) *
                        ((q == 2) ? 1.f : 0.5f);   // sigma gates prescaled x0.5
            if (q < 3) {
                g_xgp[rowoff + u * 4 + q] = val;
            } else {                 // o_u: duplicated into upper-lane slots
                if (u < 12) g_xgp[rowoff + (20 + u) * 4 + 0] = val;
                if (u >= 8) g_xgp[rowoff + (12 + u) * 4 + 1] = val;
            }
        }
    }
}

// ---------------------------------------------------------------------------
// Kernel B: single-warp scan.
//   lane l<20: slot0=i_l, slot1=f_l, slot2=g_l  (c-update needs NO shuffles)
//   lane l>=20: slot0=o_{l-20}, slot1=o_{l-12}, slot2=dummy(0)
//   o_u gathered via 2 shfl + sel, overlapped with tanh(c).
// ---------------------------------------------------------------------------
__global__ void __launch_bounds__(32, 1)
lstm_scan_kernel(const float* __restrict__ h_state,
                 const float* __restrict__ c_state,
                 const float* __restrict__ W_hh,
                 float* __restrict__ out) {
    __shared__ __align__(16) float hsm[2][32];

    const int l = threadIdx.x;
    const unsigned FULLM = 0xffffffffu;

    const int G0 = (l < 20) ? l        : (40 + l);   // i_l  | o_{l-20} (gates 60..71)
    const int G1 = (l < 20) ? (20 + l) : (48 + l);   // f_l  | o_{l-12} (gates 68..79)
    const int G2 = (l < 20) ? (40 + l) : 0;          // g_l  | dummy
    const float s2 = (l < 20) ? 1.f : 0.f;

    // k-paired W_hh rows, sigma rows prescaled x0.5 (tanh row x1)
    ull w0[10], w1[10], w2[10];
#pragma unroll
    for (int m = 0; m < 10; ++m) {
        w0[m] = pack2(0.5f * W_hh[G0 * HID + 2 * m], 0.5f * W_hh[G0 * HID + 2 * m + 1]);
        w1[m] = pack2(0.5f * W_hh[G1 * HID + 2 * m], 0.5f * W_hh[G1 * HID + 2 * m + 1]);
        w2[m] = pack2(s2   * W_hh[G2 * HID + 2 * m], s2   * W_hh[G2 * HID + 2 * m + 1]);
    }

    float c = c_state[(l < HID) ? l : 0];
    float h = 0.f;
    if (l < HID) hsm[0][l] = h_state[l];
    __syncwarp();

    const float4* xq = (const float4*)g_xgp;   // row stride: 32 float4

    float4 ring[4];
#pragma unroll
    for (int i = 0; i < 4; ++i) ring[i] = __ldg(&xq[(size_t)i * 32 + l]);

#define STEP(P, COMP, RBUF, WBUF) {                                          \
    float4 xv = ring[P];                                                     \
    int tp = t + (P) + 4; if (tp > T_LEN - 1) tp = T_LEN - 1;                \
    ring[P] = __ldg(&xq[(size_t)tp * 32 + l]);                               \
    const ull* hp = (const ull*)hsm[RBUF];                                   \
    ull a0 = pack2(xv.x, 0.f);                                               \
    ull b0 = pack2(xv.y, 0.f);                                               \
    ull d0 = pack2(xv.z, 0.f);                                               \
    ull he = hp[0], ho = hp[1];                                              \
    ffma2(a0, w0[0], he); ffma2(b0, w1[0], he); ffma2(d0, w2[0], he);        \
    ull a1 = mul2(w0[1], ho);                                                \
    ull b1 = mul2(w1[1], ho);                                                \
    ull d1 = mul2(w2[1], ho);                                                \
    _Pragma("unroll")                                                        \
    for (int m = 2; m < 10; m += 2) {                                        \
        ull hm = hp[m], hn = hp[m + 1];                                      \
        ffma2(a0, w0[m], hm); ffma2(a1, w0[m + 1], hn);                      \
        ffma2(b0, w1[m], hm); ffma2(b1, w1[m + 1], hn);                      \
        ffma2(d0, w2[m], hm); ffma2(d1, w2[m + 1], hn);                      \
    }                                                                        \
    float lo, hi, pre0, pre1, pre2;                                          \
    unpack2(fadd2(a0, a1), lo, hi); pre0 = lo + hi;                          \
    unpack2(fadd2(b0, b1), lo, hi); pre1 = lo + hi;                          \
    unpack2(fadd2(d0, d1), lo, hi); pre2 = lo + hi;                          \
    float i_a = fmaf(0.5f, tanh_mufu(pre0), 0.5f);                           \
    float f_a = fmaf(0.5f, tanh_mufu(pre1), 0.5f);                           \
    float g_a = tanh_mufu(pre2);                                             \
    float oA = __shfl_sync(FULLM, i_a, l + 20);                              \
    float oB = __shfl_sync(FULLM, f_a, l + 12);                              \
    c = fmaf(f_a, c, i_a * g_a);                                             \
    float tc = tanh_mufu(c);                                                 \
    float ov = (l < 12) ? oA : oB;                                           \
    h = ov * tc;                                                             \
    if (l < HID) hsm[WBUF][l] = h;                                           \
    __syncwarp();                                                            \
    COMP = h; }

    for (int t = 0; t < T_LEN; t += 4) {
        float4 hb;
        STEP(0, hb.x, 0, 1)
        STEP(1, hb.y, 1, 0)
        STEP(2, hb.z, 0, 1)
        STEP(3, hb.w, 1, 0)
        if (l < HID)
            *(float4*)(g_hT + (size_t)l * T_LEN + t) = hb;
    }
#undef STEP

    if (l < HID) {
        out[T_LEN + l]       = h;
        out[T_LEN + HID + l] = c;
    }
}

// ---------------------------------------------------------------------------
// Kernel C: y[t] = sum_u g_hT[u][t] * W_out[u] + b_out
// ---------------------------------------------------------------------------
__global__ void out_proj_kernel(const float* __restrict__ W_out,
                                const float* __restrict__ b_out,
                                float* __restrict__ out) {
    __shared__ float w[HID];
    __shared__ float b0;
    if (threadIdx.x < HID) w[threadIdx.x] = W_out[threadIdx.x];
    if (threadIdx.x == 0)  b0 = b_out[0];
    __syncthreads();

    int t = blockIdx.x * blockDim.x + threadIdx.x;
    if (t < T_LEN) {
        float acc = 0.f;
#pragma unroll
        for (int uu = 0; uu < HID; ++uu)
            acc = fmaf(g_hT[(size_t)uu * T_LEN + t], w[uu], acc);
        out[t] = acc + b0;
    }
}

// ---------------------------------------------------------------------------
extern "C" void kernel_launch(void* const* d_in, const int* in_sizes, int n_in,
                              void* d_out, int out_size) {
    const float* x       = (const float*)d_in[0];
    const float* h_state = (const float*)d_in[1];
    const float* c_state = (const float*)d_in[2];
    const float* W_ih    = (const float*)d_in[3];
    const float* W_hh    = (const float*)d_in[4];
    const float* b_ih    = (const float*)d_in[5];
    const float* b_hh    = (const float*)d_in[6];
    const float* W_out   = (const float*)d_in[7];
    const float* b_out   = (const float*)d_in[8];
    float* out = (float*)d_out;

    gemm_xg_kernel<<<T_LEN / 64, 256>>>(x, W_ih, b_ih, b_hh);
    lstm_scan_kernel<<<1, 32>>>(h_state, c_state, W_hh, out);
    out_proj_kernel<<<(T_LEN + 255) / 256, 256>>>(W_out, b_out, out);
}